// round 9
// baseline (speedup 1.0000x reference)
#include <cuda_runtime.h>
#include <cuda_bf16.h>
#include <cstdint>

// Problem constants
#define SD      16384        // S*D
#define NJ      22           // 14 alpha cols + 8 beta cols
#define NJP     24           // padded (2 zero cols)
#define BN      2048         // B*N
#define KC      16           // k-chunks (1024 floats each)
#define MT      16           // m-tiles of 128 bn
#define NTILE   16           // 64-k tiles per chunk
#define KT_TOT  256          // total 64-k tiles (SD/64)

typedef unsigned long long ull;

// g_Wf: B operand pre-baked in mma.m16n8k16 B-fragment layout.
// [kt][ks 0..3][ng 0..2][lane 0..31] -> uint2 {b0, b1}:
//   j = ng*8 + lane/4,  k0 = kt*64 + ks*16 + (lane%4)*2
//   b0 = bf16x2( w[j][k0],   w[j][k0+1] )
//   b1 = bf16x2( w[j][k0+8], w[j][k0+9] )
// with w[j][k] = (gamma[k]+1) * W[k][j], j>=22 -> 0.
__device__ __align__(16) uint2 g_Wf[KT_TOT * 12 * 32];
__device__ float g_part[KC][BN][NJP];
__device__ float g_ss[KC][BN];
__device__ float g_M[BN * 64];

__device__ __forceinline__ uint32_t pack_bf16x2(float lo, float hi) {
    __nv_bfloat162 h = __float22bfloat162_rn(make_float2(lo, hi));
    return *reinterpret_cast<uint32_t*>(&h);
}

__device__ __forceinline__ void mma_bf16(float* d, const uint32_t* a, uint2 b) {
    asm volatile(
        "mma.sync.aligned.m16n8k16.row.col.f32.bf16.bf16.f32 "
        "{%0,%1,%2,%3}, {%4,%5,%6,%7}, {%8,%9}, {%0,%1,%2,%3};"
        : "+f"(d[0]), "+f"(d[1]), "+f"(d[2]), "+f"(d[3])
        : "r"(a[0]), "r"(a[1]), "r"(a[2]), "r"(a[3]), "r"(b.x), "r"(b.y));
}

// ---------------------------------------------------------------------------
// Kernel P: bake B fragments (gamma folded, bf16). One thread per uint2.
// ---------------------------------------------------------------------------
__global__ void k_prepW(const float* __restrict__ gamma,
                        const float* __restrict__ Wa,
                        const float* __restrict__ Wb) {
    int i = blockIdx.x * blockDim.x + threadIdx.x;
    if (i >= KT_TOT * 12 * 32) return;
    int kt   = i / 384;
    int rem  = i - kt * 384;
    int ks   = rem / 96;
    int ng   = (rem / 32) % 3;
    int lane = rem & 31;
    int quad = lane >> 2, pos = lane & 3;
    int j  = ng * 8 + quad;
    int k0 = kt * 64 + ks * 16 + pos * 2;

    float w[4] = {0.f, 0.f, 0.f, 0.f};
    if (j < 22) {
        #pragma unroll
        for (int e = 0; e < 4; e++) {
            int k = k0 + (e >> 1) * 8 + (e & 1);
            float ww = (j < 14) ? Wa[(size_t)k * 14 + j] : Wb[(size_t)k * 8 + (j - 14)];
            w[e] = (gamma[k] + 1.0f) * ww;
        }
    }
    g_Wf[i] = make_uint2(pack_bf16x2(w[0], w[1]), pack_bf16x2(w[2], w[3]));
}

// ---------------------------------------------------------------------------
// Kernel A: tensor-core reductions via warp-level bf16 mma.sync.
// grid=(MT, KC) = 256 CTAs, 256 threads. Warp w owns rows [w*16, w*16+16)
// of the 128-bn m-tile, scanning 1024 k. Register-double-buffered A loads.
// No smem, no syncs.
// ---------------------------------------------------------------------------
__global__ __launch_bounds__(256) void k_reduce(const float* __restrict__ resid) {
    const int warp = threadIdx.x >> 5;
    const int lane = threadIdx.x & 31;
    const int quad = lane >> 2, pos = lane & 3;
    const int mt = blockIdx.x, c2 = blockIdx.y;
    const int b = mt >> 3, nbase = (mt & 7) * 128;
    const int s = c2 >> 1;

    const int row_lo = warp * 16 + quad;       // fragment rows quad / quad+8
    const float2* r2 = reinterpret_cast<const float2*>(resid);
    const size_t off_lo = (size_t)b * 8388608u + (size_t)s * 1048576u
                        + (size_t)(nbase + row_lo) * 1024u + (size_t)(c2 & 1) * 512u;
    const size_t off_hi = off_lo + 8u * 1024u;

    float acc[3][4];
    #pragma unroll
    for (int ng = 0; ng < 3; ng++)
        #pragma unroll
        for (int e = 0; e < 4; e++) acc[ng][e] = 0.0f;
    float ss_lo = 0.0f, ss_hi = 0.0f;

    // register double buffer for A tiles
    float2 av[2][4][4];

    auto load_tile = [&](int t, int buf) {
        const int kb2 = t * 32 + pos;          // float2 index of k = t*64+pos*2
        #pragma unroll
        for (int ks = 0; ks < 4; ks++) {
            const int c0 = kb2 + ks * 8;
            av[buf][ks][0] = r2[off_lo + c0];
            av[buf][ks][1] = r2[off_hi + c0];
            av[buf][ks][2] = r2[off_lo + c0 + 4];   // k+8
            av[buf][ks][3] = r2[off_hi + c0 + 4];
        }
    };

    load_tile(0, 0);

    #pragma unroll 1
    for (int t = 0; t < NTILE; t++) {
        const int buf = t & 1;
        // prefetch next tile first (hidden under this tile's compute)
        if (t + 1 < NTILE) load_tile(t + 1, buf ^ 1);

        // B fragments: 12 coalesced uint2 (L1-resident, shared by all warps)
        uint2 bv[12];
        const uint2* wt = g_Wf + (size_t)(c2 * NTILE + t) * 384 + lane;
        #pragma unroll
        for (int i = 0; i < 12; i++) bv[i] = wt[i * 32];

        #pragma unroll
        for (int ks = 0; ks < 4; ks++) {
            float2 v0 = av[buf][ks][0], v1 = av[buf][ks][1];
            float2 v2 = av[buf][ks][2], v3 = av[buf][ks][3];
            // fp32 sumsq from the same registers
            ss_lo = fmaf(v0.x, v0.x, ss_lo);
            ss_lo = fmaf(v0.y, v0.y, ss_lo);
            ss_lo = fmaf(v2.x, v2.x, ss_lo);
            ss_lo = fmaf(v2.y, v2.y, ss_lo);
            ss_hi = fmaf(v1.x, v1.x, ss_hi);
            ss_hi = fmaf(v1.y, v1.y, ss_hi);
            ss_hi = fmaf(v3.x, v3.x, ss_hi);
            ss_hi = fmaf(v3.y, v3.y, ss_hi);
            // cvt -> bf16 A fragment
            uint32_t a[4];
            a[0] = pack_bf16x2(v0.x, v0.y);
            a[1] = pack_bf16x2(v1.x, v1.y);
            a[2] = pack_bf16x2(v2.x, v2.y);
            a[3] = pack_bf16x2(v3.x, v3.y);
            #pragma unroll
            for (int ng = 0; ng < 3; ng++)
                mma_bf16(acc[ng], a, bv[ks * 3 + ng]);
        }
    }

    // store dot partials: D frag (m16n8): c0,c1 -> row quad, cols pos*2,+1
    const int bn_lo = mt * 128 + row_lo;
    #pragma unroll
    for (int ng = 0; ng < 3; ng++) {
        const int j0 = ng * 8 + pos * 2;
        *reinterpret_cast<float2*>(&g_part[c2][bn_lo][j0]) =
            make_float2(acc[ng][0], acc[ng][1]);
        *reinterpret_cast<float2*>(&g_part[c2][bn_lo + 8][j0]) =
            make_float2(acc[ng][2], acc[ng][3]);
    }
    // sumsq: reduce across the 4 lanes sharing this quad
    #pragma unroll
    for (int o = 1; o < 4; o <<= 1) {
        ss_lo += __shfl_xor_sync(0xffffffffu, ss_lo, o, 4);
        ss_hi += __shfl_xor_sync(0xffffffffu, ss_hi, o, 4);
    }
    if (pos == 0) {
        g_ss[c2][bn_lo]     = ss_lo;
        g_ss[c2][bn_lo + 8] = ss_hi;
    }
}

// ---------------------------------------------------------------------------
// Kernel B: per-(b,n) scalar epilogue -> 8x8 mixing matrix M
// ---------------------------------------------------------------------------
__global__ void k_mix(const float* __restrict__ salpha,
                      const float* __restrict__ pbs,
                      const float* __restrict__ rscale,
                      const float* __restrict__ sbeta,
                      const float* __restrict__ hps) {
    int bn = blockIdx.x * blockDim.x + threadIdx.x;
    if (bn >= BN) return;

    float dot[NJ];
    #pragma unroll
    for (int j = 0; j < NJ; j++) {
        float v = 0.0f;
        #pragma unroll
        for (int c = 0; c < KC; c++) v += g_part[c][bn][j];
        dot[j] = v;
    }
    float sumsq = 0.0f;
    #pragma unroll
    for (int c = 0; c < KC; c++) sumsq += g_ss[c][bn];

    float scale = rsqrtf(fmaxf(sumsq, 1e-24f)) * 128.0f;  // sqrt(16384)=128
    float ps = pbs[0], rs = rscale[0], hp = hps[0];

    // w_pre = softmax(ps * dyn_pre + static_alpha[:8])
    float l[8], mx = -1e30f;
    #pragma unroll
    for (int i = 0; i < 8; i++) {
        l[i] = ps * (scale * dot[i]) + salpha[i];
        mx = fmaxf(mx, l[i]);
    }
    float e[8], sum = 0.0f;
    #pragma unroll
    for (int i = 0; i < 8; i++) { e[i] = expf(l[i] - mx); sum += e[i]; }
    float inv_sum = 1.0f / sum;
    float wpre[8];
    #pragma unroll
    for (int i = 0; i < 8; i++) wpre[i] = e[i] * inv_sum;

    // pairwise softmax first elements
    float p[3];
    #pragma unroll
    for (int k = 0; k < 3; k++) {
        float c0 = rs * (scale * dot[8 + 2 * k])     + salpha[8 + 2 * k];
        float c1 = rs * (scale * dot[8 + 2 * k + 1]) + salpha[8 + 2 * k + 1];
        p[k] = 1.0f / (1.0f + expf(c1 - c0));
    }
    // Kron: H[s][t] = h[s^t]
    float h[8];
    #pragma unroll
    for (int x = 0; x < 8; x++) {
        float f0 = (x & 4) ? (1.0f - p[0]) : p[0];
        float f1 = (x & 2) ? (1.0f - p[1]) : p[1];
        float f2 = (x & 1) ? (1.0f - p[2]) : p[2];
        h[x] = f0 * f1 * f2;
    }
    float beta[8];
    #pragma unroll
    for (int t = 0; t < 8; t++)
        beta[t] = 1.0f / (1.0f + expf(-(hp * (scale * dot[14 + t]) + sbeta[t])));

    float* Mo = &g_M[bn * 64];
    #pragma unroll
    for (int s = 0; s < 8; s++)
        #pragma unroll
        for (int t = 0; t < 8; t++)
            Mo[s * 8 + t] = h[s ^ t] + beta[t] * wpre[s];
}

// ---------------------------------------------------------------------------
// Kernel C: out[t,d] = sum_s M[s][t] * r[s,d].  grid=(BN, 2). fp32 residuals.
// ---------------------------------------------------------------------------
__global__ __launch_bounds__(256) void k_apply(const float* __restrict__ resid,
                                               float* __restrict__ out) {
    const int bn = blockIdx.x;
    const int b = bn >> 10, n = bn & 1023;

    __shared__ float Ms[64];
    if (threadIdx.x < 64) Ms[threadIdx.x] = g_M[bn * 64 + threadIdx.x];
    __syncthreads();

    float M[64];
    #pragma unroll
    for (int i = 0; i < 64; i++) M[i] = Ms[i];

    const size_t base = (size_t)b * 16777216u + (size_t)n * 2048u;
    const int d = blockIdx.y * 1024 + threadIdx.x * 4;

    float4 acc[8];
    #pragma unroll
    for (int t = 0; t < 8; t++) acc[t] = make_float4(0.f, 0.f, 0.f, 0.f);

    #pragma unroll
    for (int s = 0; s < 8; s++) {
        float4 r4 = *reinterpret_cast<const float4*>(resid + base + (size_t)s * 2097152u + d);
        #pragma unroll
        for (int t = 0; t < 8; t++) {
            float m = M[s * 8 + t];
            acc[t].x += m * r4.x;
            acc[t].y += m * r4.y;
            acc[t].z += m * r4.z;
            acc[t].w += m * r4.w;
        }
    }
    #pragma unroll
    for (int t = 0; t < 8; t++)
        *reinterpret_cast<float4*>(out + base + (size_t)t * 2097152u + d) = acc[t];
}

// ---------------------------------------------------------------------------
extern "C" void kernel_launch(void* const* d_in, const int* in_sizes, int n_in,
                              void* d_out, int out_size) {
    const float* resid  = (const float*)d_in[0];   // residuals (B*S, N, D)
    const float* gamma  = (const float*)d_in[1];   // (S*D,)
    const float* salpha = (const float*)d_in[2];   // (S+T,) = 14
    const float* Wa     = (const float*)d_in[3];   // (S*D, 14)
    const float* pbs    = (const float*)d_in[4];   // (1,)
    const float* rs     = (const float*)d_in[5];   // (1,)
    const float* sbeta  = (const float*)d_in[6];   // (S,) = 8
    const float* Wb     = (const float*)d_in[7];   // (S*D, 8)
    const float* hps    = (const float*)d_in[8];   // scalar
    float* out = (float*)d_out;

    k_prepW<<<(KT_TOT * 12 * 32 + 255) / 256, 256>>>(gamma, Wa, Wb);
    k_reduce<<<dim3(MT, KC), 256>>>(resid);
    k_mix<<<BN / 256, 256>>>(salpha, pbs, rs, sbeta, hps);
    k_apply<<<dim3(BN, 2), 256>>>(resid, out);
}

// round 10
// speedup vs baseline: 1.2799x; 1.2799x over previous
#include <cuda_runtime.h>
#include <cuda_bf16.h>
#include <cstdint>

// Problem constants
#define SD      16384        // S*D
#define NJ      22           // 14 alpha cols + 8 beta cols
#define NJP     24           // padded (2 zero cols)
#define BN      2048         // B*N
#define KC      16           // k-chunks (1024 floats each)
#define MT      16           // m-tiles of 128 bn
#define NTILE   16           // 64-k tiles per chunk
#define KT_TOT  256          // total 64-k tiles (SD/64)

typedef unsigned long long ull;

// g_Wf: B operand pre-baked in mma.m16n8k16 B-fragment layout.
// [kt][ks 0..3][ng 0..2][lane 0..31] -> uint2 {b0, b1}:
//   j = ng*8 + lane/4,  k0 = kt*64 + ks*16 + (lane%4)*2
//   b0 = bf16x2( w[j][k0],   w[j][k0+1] )
//   b1 = bf16x2( w[j][k0+8], w[j][k0+9] )
// with w[j][k] = (gamma[k]+1) * W[k][j], j>=22 -> 0.
__device__ __align__(16) uint2 g_Wf[KT_TOT * 12 * 32];
__device__ float g_part[KC][BN][NJP];
__device__ float g_ss[KC][BN];
__device__ float g_M[BN * 64];

__device__ __forceinline__ uint32_t pack_bf16x2(float lo, float hi) {
    __nv_bfloat162 h = __float22bfloat162_rn(make_float2(lo, hi));
    return *reinterpret_cast<uint32_t*>(&h);
}

__device__ __forceinline__ void mma_bf16(float* d, const uint32_t* a, uint2 b) {
    asm volatile(
        "mma.sync.aligned.m16n8k16.row.col.f32.bf16.bf16.f32 "
        "{%0,%1,%2,%3}, {%4,%5,%6,%7}, {%8,%9}, {%0,%1,%2,%3};"
        : "+f"(d[0]), "+f"(d[1]), "+f"(d[2]), "+f"(d[3])
        : "r"(a[0]), "r"(a[1]), "r"(a[2]), "r"(a[3]), "r"(b.x), "r"(b.y));
}

// ---------------------------------------------------------------------------
// Kernel P: bake B fragments (gamma folded, bf16). One thread per uint2.
// ---------------------------------------------------------------------------
__global__ void k_prepW(const float* __restrict__ gamma,
                        const float* __restrict__ Wa,
                        const float* __restrict__ Wb) {
    int i = blockIdx.x * blockDim.x + threadIdx.x;
    if (i >= KT_TOT * 12 * 32) return;
    int kt   = i / 384;
    int rem  = i - kt * 384;
    int ks   = rem / 96;
    int ng   = (rem / 32) % 3;
    int lane = rem & 31;
    int quad = lane >> 2, pos = lane & 3;
    int j  = ng * 8 + quad;
    int k0 = kt * 64 + ks * 16 + pos * 2;

    float w[4] = {0.f, 0.f, 0.f, 0.f};
    if (j < 22) {
        #pragma unroll
        for (int e = 0; e < 4; e++) {
            int k = k0 + (e >> 1) * 8 + (e & 1);
            float ww = (j < 14) ? Wa[(size_t)k * 14 + j] : Wb[(size_t)k * 8 + (j - 14)];
            w[e] = (gamma[k] + 1.0f) * ww;
        }
    }
    g_Wf[i] = make_uint2(pack_bf16x2(w[0], w[1]), pack_bf16x2(w[2], w[3]));
}

// ---------------------------------------------------------------------------
// Kernel A: tensor-core reductions via warp-level bf16 mma.sync.
// grid=(MT, KC) = 256 CTAs, 256 threads, __launch_bounds__(256,2) so two
// CTAs co-reside per SM (4 warps/SMSP) in a single wave. Warp w owns rows
// [w*16, w*16+16) of the 128-bn m-tile, scanning 1024 k. Lean registers:
// no double-buffering (that was the R9 regression). No smem, no syncs.
// ---------------------------------------------------------------------------
__global__ __launch_bounds__(256, 2) void k_reduce(const float* __restrict__ resid) {
    const int warp = threadIdx.x >> 5;
    const int lane = threadIdx.x & 31;
    const int quad = lane >> 2, pos = lane & 3;
    const int mt = blockIdx.x, c2 = blockIdx.y;
    const int b = mt >> 3, nbase = (mt & 7) * 128;
    const int s = c2 >> 1;

    const int row_lo = warp * 16 + quad;       // fragment rows quad / quad+8
    const float2* r2 = reinterpret_cast<const float2*>(resid);
    const size_t off_lo = (size_t)b * 8388608u + (size_t)s * 1048576u
                        + (size_t)(nbase + row_lo) * 1024u + (size_t)(c2 & 1) * 512u;
    const size_t off_hi = off_lo + 8u * 1024u;

    float acc[3][4];
    #pragma unroll
    for (int ng = 0; ng < 3; ng++)
        #pragma unroll
        for (int e = 0; e < 4; e++) acc[ng][e] = 0.0f;
    float ss_lo = 0.0f, ss_hi = 0.0f;

    #pragma unroll 1
    for (int t = 0; t < NTILE; t++) {
        // A loads: 16 float2, all independent (MLP=16)
        float2 av[4][4];
        const int kb2 = t * 32 + pos;          // float2 index of k = t*64+pos*2
        #pragma unroll
        for (int ks = 0; ks < 4; ks++) {
            const int c0 = kb2 + ks * 8;
            av[ks][0] = r2[off_lo + c0];
            av[ks][1] = r2[off_hi + c0];
            av[ks][2] = r2[off_lo + c0 + 4];   // k+8
            av[ks][3] = r2[off_hi + c0 + 4];
        }
        // B fragments: 12 coalesced uint2 (L1/L2-resident, shared by all warps)
        uint2 bv[12];
        const uint2* wt = g_Wf + (size_t)(c2 * NTILE + t) * 384 + lane;
        #pragma unroll
        for (int i = 0; i < 12; i++) bv[i] = wt[i * 32];

        #pragma unroll
        for (int ks = 0; ks < 4; ks++) {
            float2 v0 = av[ks][0], v1 = av[ks][1];
            float2 v2 = av[ks][2], v3 = av[ks][3];
            // fp32 sumsq from the same registers
            ss_lo = fmaf(v0.x, v0.x, ss_lo);
            ss_lo = fmaf(v0.y, v0.y, ss_lo);
            ss_lo = fmaf(v2.x, v2.x, ss_lo);
            ss_lo = fmaf(v2.y, v2.y, ss_lo);
            ss_hi = fmaf(v1.x, v1.x, ss_hi);
            ss_hi = fmaf(v1.y, v1.y, ss_hi);
            ss_hi = fmaf(v3.x, v3.x, ss_hi);
            ss_hi = fmaf(v3.y, v3.y, ss_hi);
            // cvt -> bf16 A fragment
            uint32_t a[4];
            a[0] = pack_bf16x2(v0.x, v0.y);
            a[1] = pack_bf16x2(v1.x, v1.y);
            a[2] = pack_bf16x2(v2.x, v2.y);
            a[3] = pack_bf16x2(v3.x, v3.y);
            #pragma unroll
            for (int ng = 0; ng < 3; ng++)
                mma_bf16(acc[ng], a, bv[ks * 3 + ng]);
        }
    }

    // store dot partials: D frag (m16n8): c0,c1 -> row quad, cols pos*2,+1
    const int bn_lo = mt * 128 + row_lo;
    #pragma unroll
    for (int ng = 0; ng < 3; ng++) {
        const int j0 = ng * 8 + pos * 2;
        *reinterpret_cast<float2*>(&g_part[c2][bn_lo][j0]) =
            make_float2(acc[ng][0], acc[ng][1]);
        *reinterpret_cast<float2*>(&g_part[c2][bn_lo + 8][j0]) =
            make_float2(acc[ng][2], acc[ng][3]);
    }
    // sumsq: reduce across the 4 lanes sharing this quad
    #pragma unroll
    for (int o = 1; o < 4; o <<= 1) {
        ss_lo += __shfl_xor_sync(0xffffffffu, ss_lo, o, 4);
        ss_hi += __shfl_xor_sync(0xffffffffu, ss_hi, o, 4);
    }
    if (pos == 0) {
        g_ss[c2][bn_lo]     = ss_lo;
        g_ss[c2][bn_lo + 8] = ss_hi;
    }
}

// ---------------------------------------------------------------------------
// Kernel B: per-(b,n) scalar epilogue -> 8x8 mixing matrix M
// ---------------------------------------------------------------------------
__global__ void k_mix(const float* __restrict__ salpha,
                      const float* __restrict__ pbs,
                      const float* __restrict__ rscale,
                      const float* __restrict__ sbeta,
                      const float* __restrict__ hps) {
    int bn = blockIdx.x * blockDim.x + threadIdx.x;
    if (bn >= BN) return;

    float dot[NJ];
    #pragma unroll
    for (int j = 0; j < NJ; j++) {
        float v = 0.0f;
        #pragma unroll
        for (int c = 0; c < KC; c++) v += g_part[c][bn][j];
        dot[j] = v;
    }
    float sumsq = 0.0f;
    #pragma unroll
    for (int c = 0; c < KC; c++) sumsq += g_ss[c][bn];

    float scale = rsqrtf(fmaxf(sumsq, 1e-24f)) * 128.0f;  // sqrt(16384)=128
    float ps = pbs[0], rs = rscale[0], hp = hps[0];

    // w_pre = softmax(ps * dyn_pre + static_alpha[:8])
    float l[8], mx = -1e30f;
    #pragma unroll
    for (int i = 0; i < 8; i++) {
        l[i] = ps * (scale * dot[i]) + salpha[i];
        mx = fmaxf(mx, l[i]);
    }
    float e[8], sum = 0.0f;
    #pragma unroll
    for (int i = 0; i < 8; i++) { e[i] = expf(l[i] - mx); sum += e[i]; }
    float inv_sum = 1.0f / sum;
    float wpre[8];
    #pragma unroll
    for (int i = 0; i < 8; i++) wpre[i] = e[i] * inv_sum;

    // pairwise softmax first elements
    float p[3];
    #pragma unroll
    for (int k = 0; k < 3; k++) {
        float c0 = rs * (scale * dot[8 + 2 * k])     + salpha[8 + 2 * k];
        float c1 = rs * (scale * dot[8 + 2 * k + 1]) + salpha[8 + 2 * k + 1];
        p[k] = 1.0f / (1.0f + expf(c1 - c0));
    }
    // Kron: H[s][t] = h[s^t]
    float h[8];
    #pragma unroll
    for (int x = 0; x < 8; x++) {
        float f0 = (x & 4) ? (1.0f - p[0]) : p[0];
        float f1 = (x & 2) ? (1.0f - p[1]) : p[1];
        float f2 = (x & 1) ? (1.0f - p[2]) : p[2];
        h[x] = f0 * f1 * f2;
    }
    float beta[8];
    #pragma unroll
    for (int t = 0; t < 8; t++)
        beta[t] = 1.0f / (1.0f + expf(-(hp * (scale * dot[14 + t]) + sbeta[t])));

    float* Mo = &g_M[bn * 64];
    #pragma unroll
    for (int s = 0; s < 8; s++)
        #pragma unroll
        for (int t = 0; t < 8; t++)
            Mo[s * 8 + t] = h[s ^ t] + beta[t] * wpre[s];
}

// ---------------------------------------------------------------------------
// Kernel C: out[t,d] = sum_s M[s][t] * r[s,d].  grid=(BN, 2). fp32 residuals.
// ---------------------------------------------------------------------------
__global__ __launch_bounds__(256) void k_apply(const float* __restrict__ resid,
                                               float* __restrict__ out) {
    const int bn = blockIdx.x;
    const int b = bn >> 10, n = bn & 1023;

    __shared__ float Ms[64];
    if (threadIdx.x < 64) Ms[threadIdx.x] = g_M[bn * 64 + threadIdx.x];
    __syncthreads();

    float M[64];
    #pragma unroll
    for (int i = 0; i < 64; i++) M[i] = Ms[i];

    const size_t base = (size_t)b * 16777216u + (size_t)n * 2048u;
    const int d = blockIdx.y * 1024 + threadIdx.x * 4;

    float4 acc[8];
    #pragma unroll
    for (int t = 0; t < 8; t++) acc[t] = make_float4(0.f, 0.f, 0.f, 0.f);

    #pragma unroll
    for (int s = 0; s < 8; s++) {
        float4 r4 = *reinterpret_cast<const float4*>(resid + base + (size_t)s * 2097152u + d);
        #pragma unroll
        for (int t = 0; t < 8; t++) {
            float m = M[s * 8 + t];
            acc[t].x += m * r4.x;
            acc[t].y += m * r4.y;
            acc[t].z += m * r4.z;
            acc[t].w += m * r4.w;
        }
    }
    #pragma unroll
    for (int t = 0; t < 8; t++)
        *reinterpret_cast<float4*>(out + base + (size_t)t * 2097152u + d) = acc[t];
}

// ---------------------------------------------------------------------------
extern "C" void kernel_launch(void* const* d_in, const int* in_sizes, int n_in,
                              void* d_out, int out_size) {
    const float* resid  = (const float*)d_in[0];   // residuals (B*S, N, D)
    const float* gamma  = (const float*)d_in[1];   // (S*D,)
    const float* salpha = (const float*)d_in[2];   // (S+T,) = 14
    const float* Wa     = (const float*)d_in[3];   // (S*D, 14)
    const float* pbs    = (const float*)d_in[4];   // (1,)
    const float* rs     = (const float*)d_in[5];   // (1,)
    const float* sbeta  = (const float*)d_in[6];   // (S,) = 8
    const float* Wb     = (const float*)d_in[7];   // (S*D, 8)
    const float* hps    = (const float*)d_in[8];   // scalar
    float* out = (float*)d_out;

    k_prepW<<<(KT_TOT * 12 * 32 + 255) / 256, 256>>>(gamma, Wa, Wb);
    k_reduce<<<dim3(MT, KC), 256>>>(resid);
    k_mix<<<BN / 256, 256>>>(salpha, pbs, rs, sbeta, hps);
    k_apply<<<dim3(BN, 2), 256>>>(resid, out);
}